// round 12
// baseline (speedup 1.0000x reference)
#include <cuda_runtime.h>
#include <cuda_bf16.h>

// BentPrototypeQuantizer — R12: last geometry probe (512-thread CTAs).
//
// Math (proved R0, rel_err=0.0 across 11 rounds): reference codebook == ALL
// 64 vertices of {-1,+1}^6 (bent functions + complements cover the cube;
// k=64 == unique count). Nearest vertex separable: q_d = (x_d>0)?+1:-1
// (compare form keeps x==+0.0 -> -1 tie). Pure sign stream, 25.2MB each way.
//
// Locked from R6-R11: one 256-bit load + one 256-bit store per thread,
// ld.nc + L2::evict_last on input, L2::evict_first on output, regs=18.
// Single variable this round: THREADS 256 -> 512 (768 CTAs, 64KB contiguous
// tile per CTA for better L2-partition locality, fewer CTA drain events).
// 256-thread variant (9.02/9.12/9.12/9.12 e2e) is the fallback if this
// regresses.

#define THREADS 512
#define FLOATS_PER_BLOCK (THREADS * 8)   // 4096 floats = 16KB per CTA

__global__ void __launch_bounds__(THREADS, 4)
bent_quantize_v8(const float* __restrict__ x, float* __restrict__ out) {
    size_t base = (size_t)blockIdx.x * FLOATS_PER_BLOCK + (size_t)threadIdx.x * 8;

    float a[8];
    const float* p = x + base;
    asm volatile(
        "ld.global.nc.L2::evict_last.v8.f32 {%0,%1,%2,%3,%4,%5,%6,%7}, [%8];"
        : "=f"(a[0]), "=f"(a[1]), "=f"(a[2]), "=f"(a[3]),
          "=f"(a[4]), "=f"(a[5]), "=f"(a[6]), "=f"(a[7])
        : "l"(p));

    float q[8];
    #pragma unroll
    for (int j = 0; j < 8; j++)
        q[j] = (a[j] > 0.0f) ? 1.0f : -1.0f;

    float* po = out + base;
    asm volatile(
        "st.global.L2::evict_first.v8.f32 [%0], {%1,%2,%3,%4,%5,%6,%7,%8};"
        :: "l"(po),
           "f"(q[0]), "f"(q[1]), "f"(q[2]), "f"(q[3]),
           "f"(q[4]), "f"(q[5]), "f"(q[6]), "f"(q[7])
        : "memory");
}

// Generic fallback: any element count.
__global__ void __launch_bounds__(256)
bent_quantize_generic(const float* __restrict__ x, float* __restrict__ out, int n) {
    int i = blockIdx.x * blockDim.x + threadIdx.x;
    int stride = gridDim.x * blockDim.x;
    for (; i < n; i += stride) {
        float v = x[i];
        out[i] = (v > 0.0f) ? 1.0f : -1.0f;
    }
}

extern "C" void kernel_launch(void* const* d_in, const int* in_sizes, int n_in,
                              void* d_out, int out_size) {
    const float* x = (const float*)d_in[0];
    float* out = (float*)d_out;
    int n = in_sizes[0];

    if ((n % FLOATS_PER_BLOCK) == 0) {
        int blocks = n / FLOATS_PER_BLOCK;   // 1536 for the bench shape
        bent_quantize_v8<<<blocks, THREADS>>>(x, out);
    } else {
        int blocks = (n + 255) / 256;
        if (blocks > 8192) blocks = 8192;
        if (blocks < 1) blocks = 1;
        bent_quantize_generic<<<blocks, 256>>>(x, out, n);
    }
}

// round 13
// speedup vs baseline: 1.1018x; 1.1018x over previous
#include <cuda_runtime.h>
#include <cuda_bf16.h>

// BentPrototypeQuantizer — FINAL (converged; 256-thread config, best of a
// 12-round single-variable search).
//
// Math (proved R0, rel_err=0.0 every round): the reference codebook is ALL 64
// vertices of {-1,+1}^6 — each bent function appears with its complement, so
// their truth-table supports union to the entire 6-cube, and k=64 equals the
// unique-vertex count (the FPS step is a no-op permutation). Nearest-vertex
// quantization on the full hypercube is separable per coordinate:
//   q_d = (x_d > 0) ? +1 : -1
// (compare form preserves the x==+0.0 -> -1 tie from np.unique lex order +
// argmin-first). The (B*N)x64x6 distance search + argmin + gather collapses
// to an elementwise sign stream: 25.2 MB read + 25.2 MB written.
//
// Perf (R1-R12 search): converged at ~5.5 TB/s combined R+W (achieved
// mixed-direction DRAM ceiling). Optimal config — 256 threads x 3072 CTAs,
// exactly one 256-bit load + one 256-bit store per thread (regs=18,
// unpredicated exact tile); input ld.nc + L2::evict_last, output
// L2::evict_first. e2e samples: 9.02/9.12/9.12/9.12 us.
// Falsified: ITEMS=4/8 batching, 128- and 512-thread CTAs, st.wt,
// predicated bodies, all other CTA counts 768-6144.

#define THREADS 256
#define FLOATS_PER_BLOCK (THREADS * 8)   // 2048 floats = 8KB per CTA

__global__ void __launch_bounds__(THREADS, 8)
bent_quantize_v8(const float* __restrict__ x, float* __restrict__ out) {
    size_t base = (size_t)blockIdx.x * FLOATS_PER_BLOCK + (size_t)threadIdx.x * 8;

    float a[8];
    const float* p = x + base;
    asm volatile(
        "ld.global.nc.L2::evict_last.v8.f32 {%0,%1,%2,%3,%4,%5,%6,%7}, [%8];"
        : "=f"(a[0]), "=f"(a[1]), "=f"(a[2]), "=f"(a[3]),
          "=f"(a[4]), "=f"(a[5]), "=f"(a[6]), "=f"(a[7])
        : "l"(p));

    float q[8];
    #pragma unroll
    for (int j = 0; j < 8; j++)
        q[j] = (a[j] > 0.0f) ? 1.0f : -1.0f;

    float* po = out + base;
    asm volatile(
        "st.global.L2::evict_first.v8.f32 [%0], {%1,%2,%3,%4,%5,%6,%7,%8};"
        :: "l"(po),
           "f"(q[0]), "f"(q[1]), "f"(q[2]), "f"(q[3]),
           "f"(q[4]), "f"(q[5]), "f"(q[6]), "f"(q[7])
        : "memory");
}

// Generic fallback: any element count.
__global__ void __launch_bounds__(256)
bent_quantize_generic(const float* __restrict__ x, float* __restrict__ out, int n) {
    int i = blockIdx.x * blockDim.x + threadIdx.x;
    int stride = gridDim.x * blockDim.x;
    for (; i < n; i += stride) {
        float v = x[i];
        out[i] = (v > 0.0f) ? 1.0f : -1.0f;
    }
}

extern "C" void kernel_launch(void* const* d_in, const int* in_sizes, int n_in,
                              void* d_out, int out_size) {
    const float* x = (const float*)d_in[0];
    float* out = (float*)d_out;
    int n = in_sizes[0];

    if ((n % FLOATS_PER_BLOCK) == 0) {
        int blocks = n / FLOATS_PER_BLOCK;   // 3072 for the bench shape
        bent_quantize_v8<<<blocks, THREADS>>>(x, out);
    } else {
        int blocks = (n + 255) / 256;
        if (blocks > 8192) blocks = 8192;
        if (blocks < 1) blocks = 1;
        bent_quantize_generic<<<blocks, 256>>>(x, out, n);
    }
}

// round 14
// speedup vs baseline: 1.1095x; 1.0071x over previous
#include <cuda_runtime.h>
#include <cuda_bf16.h>

// BentPrototypeQuantizer — FINAL (R6 form: no cache hints; best profile AND
// tied-best e2e of a 13-round single-variable search).
//
// Math (proved R0, rel_err=0.0 every round): the reference codebook is ALL 64
// vertices of {-1,+1}^6 — each bent function appears with its complement, so
// their truth-table supports union to the entire 6-cube, and k=64 equals the
// unique-vertex count (the FPS step is a no-op permutation). Nearest-vertex
// quantization on the full hypercube is separable per coordinate:
//   q_d = (x_d > 0) ? +1 : -1
// (compare form preserves the x==+0.0 -> -1 tie from np.unique lex order +
// argmin-first). The (B*N)x64x6 distance search + argmin + gather collapses
// to an elementwise sign stream: 25.2 MB read + 25.2 MB written.
//
// Perf (R1-R13): converged at ~5.5 TB/s combined R+W (achieved mixed-
// direction DRAM ceiling). Optimal config: 256 threads x 3072 CTAs, exactly
// one 256-bit load + one 256-bit store per thread (regs=18, unpredicated
// exact tile), NO L2 eviction hints — cold-cache profiles showed the
// evict_last/evict_first pair costs ~2-3% (L2 capacity pinned away from the
// write-allocate stream) and the warm-replay benefit never materialized.
// Falsified: ITEMS=4/8, 128/512-thread CTAs, st.wt, evict hints,
// predicated bodies, all CTA counts 768-6144 other than 3072.

#define THREADS 256
#define FLOATS_PER_BLOCK (THREADS * 8)   // 2048 floats = 8KB per CTA

__global__ void __launch_bounds__(THREADS, 8)
bent_quantize_v8(const float* __restrict__ x, float* __restrict__ out) {
    size_t base = (size_t)blockIdx.x * FLOATS_PER_BLOCK + (size_t)threadIdx.x * 8;

    float a[8];
    const float* p = x + base;
    asm volatile(
        "ld.global.nc.v8.f32 {%0,%1,%2,%3,%4,%5,%6,%7}, [%8];"
        : "=f"(a[0]), "=f"(a[1]), "=f"(a[2]), "=f"(a[3]),
          "=f"(a[4]), "=f"(a[5]), "=f"(a[6]), "=f"(a[7])
        : "l"(p));

    float q[8];
    #pragma unroll
    for (int j = 0; j < 8; j++)
        q[j] = (a[j] > 0.0f) ? 1.0f : -1.0f;

    float* po = out + base;
    asm volatile(
        "st.global.v8.f32 [%0], {%1,%2,%3,%4,%5,%6,%7,%8};"
        :: "l"(po),
           "f"(q[0]), "f"(q[1]), "f"(q[2]), "f"(q[3]),
           "f"(q[4]), "f"(q[5]), "f"(q[6]), "f"(q[7])
        : "memory");
}

// Generic fallback: any element count.
__global__ void __launch_bounds__(256)
bent_quantize_generic(const float* __restrict__ x, float* __restrict__ out, int n) {
    int i = blockIdx.x * blockDim.x + threadIdx.x;
    int stride = gridDim.x * blockDim.x;
    for (; i < n; i += stride) {
        float v = x[i];
        out[i] = (v > 0.0f) ? 1.0f : -1.0f;
    }
}

extern "C" void kernel_launch(void* const* d_in, const int* in_sizes, int n_in,
                              void* d_out, int out_size) {
    const float* x = (const float*)d_in[0];
    float* out = (float*)d_out;
    int n = in_sizes[0];

    if ((n % FLOATS_PER_BLOCK) == 0) {
        int blocks = n / FLOATS_PER_BLOCK;   // 3072 for the bench shape
        bent_quantize_v8<<<blocks, THREADS>>>(x, out);
    } else {
        int blocks = (n + 255) / 256;
        if (blocks > 8192) blocks = 8192;
        if (blocks < 1) blocks = 1;
        bent_quantize_generic<<<blocks, 256>>>(x, out, n);
    }
}